// round 4
// baseline (speedup 1.0000x reference)
#include <cuda_runtime.h>
#include <math.h>

#define Bv 32
#define Nv 512
#define Hv 128
#define NHv 8
#define HDv 16
#define FFv 512
#define NBINS 50
#define ROWS (Bv*Nv)   // 16384

// ---------------- scratch (no allocations allowed) ----------------
__device__ float g_hn[ROWS*Hv];
__device__ float g_q [ROWS*Hv];
__device__ float g_k [ROWS*Hv];
__device__ float g_v [ROWS*Hv];
__device__ float g_ao[ROWS*Hv];
__device__ float g_u [ROWS*2*FFv];

// ---------------- LayerNorm: one warp per 128-wide row ----------------
__global__ __launch_bounds__(256) void ln_kernel(
    const float* __restrict__ h,
    const float* __restrict__ gamma,
    const float* __restrict__ beta,
    float* __restrict__ out)
{
    int row  = blockIdx.x * 8 + (threadIdx.x >> 5);
    int lane = threadIdx.x & 31;
    const float4* hp = (const float4*)(h + (size_t)row * Hv);
    float4 v = hp[lane];
    float s  = v.x + v.y + v.z + v.w;
    float ss = v.x*v.x + v.y*v.y + v.z*v.z + v.w*v.w;
    #pragma unroll
    for (int off = 16; off; off >>= 1) {
        s  += __shfl_xor_sync(0xffffffffu, s,  off);
        ss += __shfl_xor_sync(0xffffffffu, ss, off);
    }
    float mu  = s * (1.0f/Hv);
    float var = ss * (1.0f/Hv) - mu*mu;
    float inv = rsqrtf(var + 1e-5f);
    float4 g4 = ((const float4*)gamma)[lane];
    float4 b4 = ((const float4*)beta)[lane];
    float4 o;
    o.x = (v.x-mu)*inv*g4.x + b4.x;
    o.y = (v.y-mu)*inv*g4.y + b4.y;
    o.z = (v.z-mu)*inv*g4.z + b4.z;
    o.w = (v.w-mu)*inv*g4.w + b4.w;
    ((float4*)(out + (size_t)row*Hv))[lane] = o;
}

// ---------------- SGEMM: C = op(A) @ W + bias (+ residual) ----------------
// 64x64 tile, BK=16, 256 threads, 4x4 micro-tile per thread.
// GLU: A element (m,k) = u[m,k] * sigmoid(u[m, FFv+k]) with row stride 2*FFv.
template<bool GLU, bool RES>
__global__ __launch_bounds__(256) void gemm_kernel(
    const float* __restrict__ A, const float* __restrict__ W,
    const float* __restrict__ bias, const float* __restrict__ R,
    float* __restrict__ C, int M, int K, int Nc)
{
    __shared__ float As[16][64];
    __shared__ float Ws[16][64];
    const int tid = threadIdx.x;
    const int tx = tid & 15, ty = tid >> 4;
    const int bm = blockIdx.y * 64, bn = blockIdx.x * 64;

    float acc[4][4];
    #pragma unroll
    for (int i=0;i<4;i++)
        #pragma unroll
        for (int j=0;j<4;j++) acc[i][j]=0.f;

    const int ar = tid >> 2, ac = (tid & 3) << 2;
    const int wr = tid >> 4, wc = (tid & 15) << 2;

    for (int k0 = 0; k0 < K; k0 += 16) {
        float4 av;
        if (GLU) {
            const float* up = A + (size_t)(bm + ar) * (2*FFv);
            float4 a1 = *(const float4*)(up + k0 + ac);
            float4 a2 = *(const float4*)(up + FFv + k0 + ac);
            av.x = a1.x / (1.f + __expf(-a2.x));
            av.y = a1.y / (1.f + __expf(-a2.y));
            av.z = a1.z / (1.f + __expf(-a2.z));
            av.w = a1.w / (1.f + __expf(-a2.w));
        } else {
            av = *(const float4*)(A + (size_t)(bm + ar) * K + k0 + ac);
        }
        As[ac+0][ar] = av.x; As[ac+1][ar] = av.y;
        As[ac+2][ar] = av.z; As[ac+3][ar] = av.w;
        *(float4*)&Ws[wr][wc] = *(const float4*)(W + (size_t)(k0 + wr) * Nc + bn + wc);
        __syncthreads();
        #pragma unroll
        for (int kk = 0; kk < 16; kk++) {
            float4 a4 = *(float4*)&As[kk][ty<<2];
            float4 b4 = *(float4*)&Ws[kk][tx<<2];
            float a[4] = {a4.x,a4.y,a4.z,a4.w};
            float b[4] = {b4.x,b4.y,b4.z,b4.w};
            #pragma unroll
            for (int i=0;i<4;i++)
                #pragma unroll
                for (int j=0;j<4;j++)
                    acc[i][j] = fmaf(a[i], b[j], acc[i][j]);
        }
        __syncthreads();
    }
    #pragma unroll
    for (int i=0;i<4;i++) {
        int cm = bm + (ty<<2) + i;
        int cn = bn + (tx<<2);
        float4 b4 = *(const float4*)(bias + cn);
        float4 o;
        o.x = acc[i][0] + b4.x; o.y = acc[i][1] + b4.y;
        o.z = acc[i][2] + b4.z; o.w = acc[i][3] + b4.w;
        if (RES) {
            float4 r4 = *(const float4*)(R + (size_t)cm * Nc + cn);
            o.x += r4.x; o.y += r4.y; o.z += r4.z; o.w += r4.w;
        }
        *(float4*)(C + (size_t)cm * Nc + cn) = o;
    }
}

// ---------------- fused attention (flash-style, per (b, head, 32-query tile)) ----
#define QT 32
#define KT 128
#define KP 20    // padded K/V smem row stride (bank-conflict free, float4-aligned)
#define SP 132   // padded S row stride

__global__ __launch_bounds__(256) void attn_kernel(
    const float* __restrict__ Q, const float* __restrict__ K,
    const float* __restrict__ V, const float* __restrict__ dist,
    const int* __restrict__ mask,     // bool shipped as int32 (nonzero = masked)
    const float* __restrict__ demb,   // [NBINS, NHv] for this layer
    const float* __restrict__ abias,  // [NHv] for this layer
    float* __restrict__ AO)
{
    __shared__ float Ks[KT*KP];
    __shared__ float Vs[KT*KP];
    __shared__ float S [QT*SP];
    __shared__ float Qs[QT*KP];
    __shared__ float rowm[QT], rowl[QT], rowscale[QT];
    __shared__ float db[NBINS];

    const int tid = threadIdx.x;
    const int qt = blockIdx.x, hh = blockIdx.y, bb = blockIdx.z;
    const int q0g = bb*Nv + qt*QT;   // first global row of this query tile

    if (tid < NBINS) db[tid] = demb[tid*NHv + hh];
    if (tid < QT)  { rowm[tid] = -1e30f; rowl[tid] = 0.f; }
    if (tid < 128) {
        int r = tid >> 2, j = (tid & 3) << 2;
        *(float4*)&Qs[r*KP + j] =
            *(const float4*)(Q + (size_t)(q0g + r)*Hv + hh*HDv + j);
    }
    __syncthreads();

    // per-thread fixed query row for the dot phase
    const int qloc = tid >> 3, kk0 = tid & 7;
    float4 qr0 = *(float4*)&Qs[qloc*KP + 0];
    float4 qr1 = *(float4*)&Qs[qloc*KP + 4];
    float4 qr2 = *(float4*)&Qs[qloc*KP + 8];
    float4 qr3 = *(float4*)&Qs[qloc*KP + 12];
    const float ab = abias[hh];

    // output accumulator mapping: 512 outputs (32q x 16d), 2 per thread
    const int od0 = tid & 15, oq0 = tid >> 4, oq1 = oq0 + 16;
    float oacc0 = 0.f, oacc1 = 0.f;

    for (int kt = 0; kt < Nv/KT; kt++) {
        const int kb = kt*KT;
        __syncthreads();   // protect Ks/Vs/S from previous iteration consumers
        // --- load K/V tile ---
        #pragma unroll
        for (int i = 0; i < 2; i++) {
            int id = tid + i*256;
            int r = id >> 2, j = (id & 3) << 2;
            size_t goff = (size_t)(bb*Nv + kb + r)*Hv + hh*HDv + j;
            *(float4*)&Ks[r*KP + j] = *(const float4*)(K + goff);
            *(float4*)&Vs[r*KP + j] = *(const float4*)(V + goff);
        }
        __syncthreads();
        // --- scores: S[q][k] = (Q.K)/sqrt(16) ---
        #pragma unroll 4
        for (int kk = 0; kk < 16; kk++) {
            int k = kk0 + (kk << 3);
            const float* kr = &Ks[k*KP];
            float4 k0 = *(const float4*)(kr+0);
            float4 k1 = *(const float4*)(kr+4);
            float4 k2 = *(const float4*)(kr+8);
            float4 k3 = *(const float4*)(kr+12);
            float d =
                qr0.x*k0.x + qr0.y*k0.y + qr0.z*k0.z + qr0.w*k0.w +
                qr1.x*k1.x + qr1.y*k1.y + qr1.z*k1.z + qr1.w*k1.w +
                qr2.x*k2.x + qr2.y*k2.y + qr2.z*k2.z + qr2.w*k2.w +
                qr3.x*k3.x + qr3.y*k3.y + qr3.z*k3.z + qr3.w*k3.w;
            S[qloc*SP + k] = d * 0.25f;
        }
        __syncthreads();
        // --- distance-bin bias + attn_bias + key mask (coalesced dist reads) ---
        #pragma unroll
        for (int i = 0; i < 16; i++) {
            int id = tid + (i << 8);
            int q = id >> 7, k = id & 127;
            float sv;
            if (mask[bb*Nv + kb + k] != 0) {
                sv = -1e9f;  // reference sets masked scores to exactly -1e9
            } else {
                float dv = dist[(size_t)(q0g + q)*Nv + kb + k];
                int bi = (int)(dv * 10.0f);
                bi = bi < 0 ? 0 : (bi > NBINS-1 ? NBINS-1 : bi);
                sv = S[q*SP + k] + db[bi] + ab;
            }
            S[q*SP + k] = sv;
        }
        __syncthreads();
        // --- online softmax stats: warp w owns rows 4w..4w+3 ---
        {
            int w = tid >> 5, lane = tid & 31;
            for (int r = (w<<2); r < (w<<2)+4; r++) {
                float* sr = &S[r*SP];
                float m = -1e30f;
                #pragma unroll
                for (int k = 0; k < 4; k++) m = fmaxf(m, sr[lane + (k<<5)]);
                #pragma unroll
                for (int off=16; off; off>>=1)
                    m = fmaxf(m, __shfl_xor_sync(0xffffffffu, m, off));
                float oldm = rowm[r];
                float nm = fmaxf(oldm, m);
                float s = 0.f;
                #pragma unroll
                for (int k = 0; k < 4; k++) {
                    float p = __expf(sr[lane + (k<<5)] - nm);
                    sr[lane + (k<<5)] = p;
                    s += p;
                }
                #pragma unroll
                for (int off=16; off; off>>=1)
                    s += __shfl_xor_sync(0xffffffffu, s, off);
                if (lane == 0) {
                    float sc = __expf(oldm - nm);
                    rowscale[r] = sc;
                    rowl[r] = rowl[r]*sc + s;
                    rowm[r] = nm;
                }
            }
        }
        __syncthreads();
        // --- O += P @ V (rescaled) ---
        {
            float a0 = 0.f, a1 = 0.f;
            const float* s0 = &S[oq0*SP];
            const float* s1 = &S[oq1*SP];
            #pragma unroll 8
            for (int k = 0; k < KT; k++) {
                float vv = Vs[k*KP + od0];
                a0 = fmaf(s0[k], vv, a0);
                a1 = fmaf(s1[k], vv, a1);
            }
            oacc0 = oacc0*rowscale[oq0] + a0;
            oacc1 = oacc1*rowscale[oq1] + a1;
        }
    }
    AO[(size_t)(q0g + oq0)*Hv + hh*HDv + od0] = oacc0 / rowl[oq0];
    AO[(size_t)(q0g + oq1)*Hv + hh*HDv + od0] = oacc1 / rowl[oq1];
}

// ---------------- launch ----------------
extern "C" void kernel_launch(void* const* d_in, const int* in_sizes, int n_in,
                              void* d_out, int out_size)
{
    const float* x    = (const float*)d_in[0];
    const float* dist = (const float*)d_in[1];
    const int*   mask = (const int*)d_in[2];
    const float* Wq  = (const float*)d_in[3];
    const float* bq  = (const float*)d_in[4];
    const float* Wk  = (const float*)d_in[5];
    const float* bk  = (const float*)d_in[6];
    const float* Wv  = (const float*)d_in[7];
    const float* bv  = (const float*)d_in[8];
    const float* Wo  = (const float*)d_in[9];
    const float* bo  = (const float*)d_in[10];
    const float* demb= (const float*)d_in[11];
    const float* ab  = (const float*)d_in[12];
    const float* g1  = (const float*)d_in[13];
    const float* b1  = (const float*)d_in[14];
    const float* g2  = (const float*)d_in[15];
    const float* b2  = (const float*)d_in[16];
    const float* Wf1 = (const float*)d_in[17];
    const float* bf1 = (const float*)d_in[18];
    const float* Wf2 = (const float*)d_in[19];
    const float* bf2 = (const float*)d_in[20];

    float* h = (float*)d_out;
    float *hn, *q, *k, *v, *ao, *u;
    cudaGetSymbolAddress((void**)&hn, g_hn);
    cudaGetSymbolAddress((void**)&q,  g_q);
    cudaGetSymbolAddress((void**)&k,  g_k);
    cudaGetSymbolAddress((void**)&v,  g_v);
    cudaGetSymbolAddress((void**)&ao, g_ao);
    cudaGetSymbolAddress((void**)&u,  g_u);

    cudaMemcpyAsync(h, x, (size_t)ROWS*Hv*sizeof(float), cudaMemcpyDeviceToDevice);

    dim3 gqkv(Hv/64,     ROWS/64);   // (2, 256)
    dim3 gff1(2*FFv/64,  ROWS/64);   // (16, 256)
    dim3 gattn(Nv/QT, NHv, Bv);      // (16, 8, 32)

    for (int l = 0; l < 3; l++) {
        ln_kernel<<<ROWS/8, 256>>>(h, g1 + l*Hv, b1 + l*Hv, hn);
        gemm_kernel<false,false><<<gqkv, 256>>>(hn, Wq + (size_t)l*Hv*Hv, bq + l*Hv, nullptr, q, ROWS, Hv, Hv);
        gemm_kernel<false,false><<<gqkv, 256>>>(hn, Wk + (size_t)l*Hv*Hv, bk + l*Hv, nullptr, k, ROWS, Hv, Hv);
        gemm_kernel<false,false><<<gqkv, 256>>>(hn, Wv + (size_t)l*Hv*Hv, bv + l*Hv, nullptr, v, ROWS, Hv, Hv);
        attn_kernel<<<gattn, 256>>>(q, k, v, dist, mask,
                                    demb + (size_t)l*NBINS*NHv, ab + l*NHv, ao);
        gemm_kernel<false,true ><<<gqkv, 256>>>(ao, Wo + (size_t)l*Hv*Hv, bo + l*Hv, h, h, ROWS, Hv, Hv);
        ln_kernel<<<ROWS/8, 256>>>(h, g2 + l*Hv, b2 + l*Hv, hn);
        gemm_kernel<false,false><<<gff1, 256>>>(hn, Wf1 + (size_t)l*Hv*2*FFv, bf1 + (size_t)l*2*FFv, nullptr, u, ROWS, Hv, 2*FFv);
        gemm_kernel<true, true ><<<gqkv, 256>>>(u,  Wf2 + (size_t)l*FFv*Hv,  bf2 + l*Hv, h, h, ROWS, FFv, Hv);
    }
}

// round 5
// speedup vs baseline: 1.7762x; 1.7762x over previous
#include <cuda_runtime.h>
#include <math.h>

#define Bv 32
#define Nv 512
#define Hv 128
#define NHv 8
#define HDv 16
#define FFv 512
#define NBINS 50
#define ROWS (Bv*Nv)   // 16384

typedef unsigned long long u64;

// ---------------- packed fp32x2 helpers (sm_103a FFMA2 path) ----------------
__device__ __forceinline__ u64 pack2(float x, float y){
    u64 r; asm("mov.b64 %0, {%1, %2};" : "=l"(r) : "f"(x), "f"(y)); return r;
}
__device__ __forceinline__ void unpack2(u64 v, float& x, float& y){
    asm("mov.b64 {%0, %1}, %2;" : "=f"(x), "=f"(y) : "l"(v));
}
__device__ __forceinline__ void fma2(u64& c, u64 a, u64 b){
    asm("fma.rn.f32x2 %0, %1, %2, %3;" : "=l"(c) : "l"(a), "l"(b), "l"(c));
}

// ---------------- scratch (no allocations allowed) ----------------
__device__ float g_hn[ROWS*Hv];
__device__ float g_q [ROWS*Hv];
__device__ float g_k [ROWS*Hv];
__device__ float g_v [ROWS*Hv];
__device__ float g_ao[ROWS*Hv];
__device__ float g_u [ROWS*2*FFv];
__device__ unsigned char g_bins[(size_t)ROWS*Nv];   // 8.4 MB, fits L2

// ---------------- distance->bin precompute (once per launch) ----------------
__global__ __launch_bounds__(256) void bins_kernel(
    const float* __restrict__ dist, unsigned char* __restrict__ bins)
{
    int i = (blockIdx.x*256 + threadIdx.x) * 4;
    float4 d = *(const float4*)(dist + i);
    int b0 = (int)(d.x*10.f); b0 = b0<0?0:(b0>NBINS-1?NBINS-1:b0);
    int b1 = (int)(d.y*10.f); b1 = b1<0?0:(b1>NBINS-1?NBINS-1:b1);
    int b2 = (int)(d.z*10.f); b2 = b2<0?0:(b2>NBINS-1?NBINS-1:b2);
    int b3 = (int)(d.w*10.f); b3 = b3<0?0:(b3>NBINS-1?NBINS-1:b3);
    uchar4 o; o.x=(unsigned char)b0; o.y=(unsigned char)b1;
    o.z=(unsigned char)b2; o.w=(unsigned char)b3;
    *(uchar4*)(bins + i) = o;
}

// ---------------- LayerNorm: one warp per 128-wide row ----------------
__global__ __launch_bounds__(256) void ln_kernel(
    const float* __restrict__ h,
    const float* __restrict__ gamma,
    const float* __restrict__ beta,
    float* __restrict__ out)
{
    int row  = blockIdx.x * 8 + (threadIdx.x >> 5);
    int lane = threadIdx.x & 31;
    const float4* hp = (const float4*)(h + (size_t)row * Hv);
    float4 v = hp[lane];
    float s  = v.x + v.y + v.z + v.w;
    float ss = v.x*v.x + v.y*v.y + v.z*v.z + v.w*v.w;
    #pragma unroll
    for (int off = 16; off; off >>= 1) {
        s  += __shfl_xor_sync(0xffffffffu, s,  off);
        ss += __shfl_xor_sync(0xffffffffu, ss, off);
    }
    float mu  = s * (1.0f/Hv);
    float var = ss * (1.0f/Hv) - mu*mu;
    float inv = rsqrtf(var + 1e-5f);
    float4 g4 = ((const float4*)gamma)[lane];
    float4 b4 = ((const float4*)beta)[lane];
    float4 o;
    o.x = (v.x-mu)*inv*g4.x + b4.x;
    o.y = (v.y-mu)*inv*g4.y + b4.y;
    o.z = (v.z-mu)*inv*g4.z + b4.z;
    o.w = (v.w-mu)*inv*g4.w + b4.w;
    ((float4*)(out + (size_t)row*Hv))[lane] = o;
}

// ---------------- SGEMM: 128x128 tile, BK=16, 8x8 micro-tile, f32x2 FMA ----
// MODE: 0 = plain, 1 = +residual, 2 = GLU(A)+residual, 3 = fused QKV (3 W/b/C)
template<int MODE>
__global__ __launch_bounds__(256) void gemm_kernel(
    const float* __restrict__ A,
    const float* __restrict__ W0, const float* __restrict__ B0, float* __restrict__ C0,
    const float* __restrict__ W1, const float* __restrict__ B1c, float* __restrict__ C1,
    const float* __restrict__ W2, const float* __restrict__ B2c, float* __restrict__ C2,
    const float* __restrict__ R, int K, int Nc)
{
    __shared__ __align__(16) float As[2][16][132];
    __shared__ __align__(16) float Ws[2][16][128];
    const int tid = threadIdx.x;
    const float *W, *bias; float* C;
    int bn;
    if (MODE == 3) {
        int s = blockIdx.x;
        W    = (s==0)?W0:((s==1)?W1:W2);
        bias = (s==0)?B0:((s==1)?B1c:B2c);
        C    = (s==0)?C0:((s==1)?C1:C2);
        bn = 0;
    } else { W = W0; bias = B0; C = C0; bn = blockIdx.x * 128; }
    const int bm = blockIdx.y * 128;
    const int tx = tid & 15, ty = tid >> 4;
    const int ar = tid >> 1, ac = (tid & 1) * 8;   // A loader: row ar, 8 cols
    const int wr = tid >> 4, wc = (tid & 15) * 8;  // W loader: row wr, 8 cols
    const int ldA = (MODE==2) ? (2*FFv) : K;
    const float* Arow = A + (size_t)(bm + ar) * ldA;
    const float* Wp   = W + (size_t)wr * Nc + bn + wc;

    u64 acc[8][4];
    #pragma unroll
    for (int i=0;i<8;i++)
        #pragma unroll
        for (int j=0;j<4;j++) acc[i][j] = 0ull;

    float4 a0v, a1v, w0v, w1v;
    #define LOADT(k0) do { \
        if (MODE==2) { \
            float4 p0 = *(const float4*)(Arow + (k0) + ac); \
            float4 p1 = *(const float4*)(Arow + (k0) + ac + 4); \
            float4 s0 = *(const float4*)(Arow + FFv + (k0) + ac); \
            float4 s1 = *(const float4*)(Arow + FFv + (k0) + ac + 4); \
            a0v.x = p0.x/(1.f+__expf(-s0.x)); a0v.y = p0.y/(1.f+__expf(-s0.y)); \
            a0v.z = p0.z/(1.f+__expf(-s0.z)); a0v.w = p0.w/(1.f+__expf(-s0.w)); \
            a1v.x = p1.x/(1.f+__expf(-s1.x)); a1v.y = p1.y/(1.f+__expf(-s1.y)); \
            a1v.z = p1.z/(1.f+__expf(-s1.z)); a1v.w = p1.w/(1.f+__expf(-s1.w)); \
        } else { \
            a0v = *(const float4*)(Arow + (k0) + ac); \
            a1v = *(const float4*)(Arow + (k0) + ac + 4); \
        } \
        w0v = *(const float4*)(Wp + (size_t)(k0)*Nc); \
        w1v = *(const float4*)(Wp + (size_t)(k0)*Nc + 4); \
    } while(0)
    #define STORET(b) do { \
        As[b][ac+0][ar]=a0v.x; As[b][ac+1][ar]=a0v.y; \
        As[b][ac+2][ar]=a0v.z; As[b][ac+3][ar]=a0v.w; \
        As[b][ac+4][ar]=a1v.x; As[b][ac+5][ar]=a1v.y; \
        As[b][ac+6][ar]=a1v.z; As[b][ac+7][ar]=a1v.w; \
        *(float4*)&Ws[b][wr][wc]   = w0v; \
        *(float4*)&Ws[b][wr][wc+4] = w1v; \
    } while(0)

    LOADT(0); STORET(0); __syncthreads();
    const int nt = K/16;
    for (int t = 0; t < nt; t++) {
        int cur = t & 1;
        if (t+1 < nt) LOADT((t+1)*16);
        #pragma unroll
        for (int kk = 0; kk < 16; kk++) {
            float4 af0 = *(float4*)&As[cur][kk][ty*8];
            float4 af1 = *(float4*)&As[cur][kk][ty*8+4];
            const u64* bp = (const u64*)&Ws[cur][kk][tx*8];
            u64 b2[4]; b2[0]=bp[0]; b2[1]=bp[1]; b2[2]=bp[2]; b2[3]=bp[3];
            u64 as2[8];
            as2[0]=pack2(af0.x,af0.x); as2[1]=pack2(af0.y,af0.y);
            as2[2]=pack2(af0.z,af0.z); as2[3]=pack2(af0.w,af0.w);
            as2[4]=pack2(af1.x,af1.x); as2[5]=pack2(af1.y,af1.y);
            as2[6]=pack2(af1.z,af1.z); as2[7]=pack2(af1.w,af1.w);
            #pragma unroll
            for (int i=0;i<8;i++)
                #pragma unroll
                for (int j=0;j<4;j++) fma2(acc[i][j], as2[i], b2[j]);
        }
        if (t+1 < nt) STORET(cur^1);
        __syncthreads();
    }
    #undef LOADT
    #undef STORET

    const int cn = bn + tx*8;
    float4 bv0 = *(const float4*)(bias + cn);
    float4 bv1 = *(const float4*)(bias + cn + 4);
    #pragma unroll
    for (int i = 0; i < 8; i++) {
        int cm = bm + ty*8 + i;
        float c[8];
        #pragma unroll
        for (int j=0;j<4;j++) unpack2(acc[i][j], c[2*j], c[2*j+1]);
        c[0]+=bv0.x; c[1]+=bv0.y; c[2]+=bv0.z; c[3]+=bv0.w;
        c[4]+=bv1.x; c[5]+=bv1.y; c[6]+=bv1.z; c[7]+=bv1.w;
        if (MODE==1 || MODE==2) {
            float4 r0 = *(const float4*)(R + (size_t)cm*Nc + cn);
            float4 r1 = *(const float4*)(R + (size_t)cm*Nc + cn + 4);
            c[0]+=r0.x; c[1]+=r0.y; c[2]+=r0.z; c[3]+=r0.w;
            c[4]+=r1.x; c[5]+=r1.y; c[6]+=r1.z; c[7]+=r1.w;
        }
        float4 o0 = make_float4(c[0],c[1],c[2],c[3]);
        float4 o1 = make_float4(c[4],c[5],c[6],c[7]);
        *(float4*)(C + (size_t)cm*Nc + cn)     = o0;
        *(float4*)(C + (size_t)cm*Nc + cn + 4) = o1;
    }
}

// ---------------- fused attention (flash-style) ----------------
#define QT 32
#define KT 128
#define KP 22    // Ks/Qs row stride: u64-aligned (88B), low LDS conflicts
#define SP 132
#define VP 132

__global__ __launch_bounds__(256) void attn_kernel(
    const float* __restrict__ Q, const float* __restrict__ Kg,
    const float* __restrict__ V, const unsigned char* __restrict__ bins,
    const int* __restrict__ mask,
    const float* __restrict__ demb, const float* __restrict__ abias,
    float* __restrict__ AO)
{
    __shared__ __align__(16) float Ks[KT*KP];
    __shared__ __align__(16) float Vt[HDv*VP];   // transposed: [d][k]
    __shared__ __align__(16) float S [QT*SP];
    __shared__ __align__(16) float Qs[QT*KP];
    __shared__ float rowm[QT], rowl[QT], rowscale[QT];
    __shared__ float db[NBINS];
    __shared__ int maskt[KT];

    const int tid = threadIdx.x;
    const int qt = blockIdx.x, hh = blockIdx.y, bb = blockIdx.z;
    const int q0g = bb*Nv + qt*QT;

    if (tid < NBINS) db[tid] = demb[tid*NHv + hh];
    if (tid < QT)  { rowm[tid] = -1e30f; rowl[tid] = 0.f; }
    if (tid < 128) {
        int r = tid >> 2, j = (tid & 3) << 2;
        float4 qv = *(const float4*)(Q + (size_t)(q0g + r)*Hv + hh*HDv + j);
        float* dst = &Qs[r*KP + j];
        *(float2*)dst     = make_float2(qv.x, qv.y);
        *(float2*)(dst+2) = make_float2(qv.z, qv.w);
    }
    __syncthreads();

    const int qg = tid >> 5;        // warp id: owns q rows 4qg..4qg+3
    const int lane = tid & 31;
    u64 q2[4][8];
    #pragma unroll
    for (int i=0;i<4;i++) {
        const u64* qr = (const u64*)&Qs[(qg*4+i)*KP];
        #pragma unroll
        for (int d=0; d<8; d++) q2[i][d] = qr[d];
    }
    const float ab = abias[hh];

    const int oq0 = tid >> 4, oq1 = oq0 + 16, od0 = tid & 15;
    float oacc0 = 0.f, oacc1 = 0.f;

    for (int kt2 = 0; kt2 < Nv/KT; kt2++) {
        const int kb = kt2*KT;
        __syncthreads();   // guard tiles vs previous-iteration consumers
        // --- load K (row-major) and V (transposed) tiles ---
        #pragma unroll
        for (int ii=0; ii<2; ii++) {
            int id = tid + ii*256;
            int r = id >> 2, j = (id & 3) << 2;
            size_t goff = (size_t)(bb*Nv + kb + r)*Hv + hh*HDv + j;
            float4 kv = *(const float4*)(Kg + goff);
            float* kd = &Ks[r*KP + j];
            *(float2*)kd     = make_float2(kv.x, kv.y);
            *(float2*)(kd+2) = make_float2(kv.z, kv.w);
            float4 vv = *(const float4*)(V + goff);
            Vt[(j+0)*VP + r] = vv.x;
            Vt[(j+1)*VP + r] = vv.y;
            Vt[(j+2)*VP + r] = vv.z;
            Vt[(j+3)*VP + r] = vv.w;
        }
        if (tid < KT) maskt[tid] = mask[bb*Nv + kb + tid];
        __syncthreads();

        // --- scores + bias + mask in one pass (4 q rows x 4 keys / thread) ---
        #pragma unroll
        for (int jj=0; jj<4; jj++) {
            int k = lane + 32*jj;
            const u64* kr = (const u64*)&Ks[k*KP];
            u64 s2[4]; s2[0]=0ull; s2[1]=0ull; s2[2]=0ull; s2[3]=0ull;
            #pragma unroll
            for (int d=0; d<8; d++) {
                u64 kv = kr[d];
                fma2(s2[0], q2[0][d], kv);
                fma2(s2[1], q2[1][d], kv);
                fma2(s2[2], q2[2][d], kv);
                fma2(s2[3], q2[3][d], kv);
            }
            bool msk = (maskt[k] != 0);
            int kglob = kb + k;
            #pragma unroll
            for (int i=0;i<4;i++) {
                float sv;
                if (msk) sv = -1e9f;   // reference: exact replacement
                else {
                    float e,o; unpack2(s2[i], e, o);
                    unsigned char bi = bins[(size_t)(q0g + qg*4 + i)*Nv + kglob];
                    sv = (e+o)*0.25f + db[bi] + ab;
                }
                S[(qg*4+i)*SP + k] = sv;
            }
        }
        __syncthreads();

        // --- online softmax stats: warp qg owns rows 4qg..4qg+3 ---
        #pragma unroll
        for (int rr=0; rr<4; rr++) {
            int r = qg*4 + rr;
            float* sr = &S[r*SP];
            float m = -1e30f;
            #pragma unroll
            for (int k=0;k<4;k++) m = fmaxf(m, sr[lane + (k<<5)]);
            #pragma unroll
            for (int off=16; off; off>>=1)
                m = fmaxf(m, __shfl_xor_sync(0xffffffffu, m, off));
            float oldm = rowm[r];
            float nm = fmaxf(oldm, m);
            float s = 0.f;
            #pragma unroll
            for (int k=0;k<4;k++) {
                float p = __expf(sr[lane + (k<<5)] - nm);
                sr[lane + (k<<5)] = p;
                s += p;
            }
            #pragma unroll
            for (int off=16; off; off>>=1)
                s += __shfl_xor_sync(0xffffffffu, s, off);
            if (lane == 0) {
                float sc = __expf(oldm - nm);
                rowscale[r] = sc;
                rowl[r] = rowl[r]*sc + s;
                rowm[r] = nm;
            }
        }
        __syncthreads();

        // --- O += P @ V  (packed over k, horizontal add at tile end) ---
        {
            u64 a0p = 0ull, a1p = 0ull;
            const u64* s0p = (const u64*)&S[oq0*SP];
            const u64* s1p = (const u64*)&S[oq1*SP];
            const u64* vp  = (const u64*)&Vt[od0*VP];
            #pragma unroll 8
            for (int k2 = 0; k2 < KT/2; k2++) {
                u64 vv = vp[k2];
                fma2(a0p, s0p[k2], vv);
                fma2(a1p, s1p[k2], vv);
            }
            float e0,o0,e1,o1;
            unpack2(a0p, e0, o0); unpack2(a1p, e1, o1);
            oacc0 = oacc0*rowscale[oq0] + (e0+o0);
            oacc1 = oacc1*rowscale[oq1] + (e1+o1);
        }
    }
    AO[(size_t)(q0g + oq0)*Hv + hh*HDv + od0] = oacc0 / rowl[oq0];
    AO[(size_t)(q0g + oq1)*Hv + hh*HDv + od0] = oacc1 / rowl[oq1];
}

// ---------------- launch ----------------
extern "C" void kernel_launch(void* const* d_in, const int* in_sizes, int n_in,
                              void* d_out, int out_size)
{
    const float* x    = (const float*)d_in[0];
    const float* dist = (const float*)d_in[1];
    const int*   mask = (const int*)d_in[2];
    const float* Wq  = (const float*)d_in[3];
    const float* bq  = (const float*)d_in[4];
    const float* Wk  = (const float*)d_in[5];
    const float* bk  = (const float*)d_in[6];
    const float* Wv  = (const float*)d_in[7];
    const float* bv  = (const float*)d_in[8];
    const float* Wo  = (const float*)d_in[9];
    const float* bo  = (const float*)d_in[10];
    const float* demb= (const float*)d_in[11];
    const float* ab  = (const float*)d_in[12];
    const float* g1  = (const float*)d_in[13];
    const float* b1  = (const float*)d_in[14];
    const float* g2  = (const float*)d_in[15];
    const float* b2  = (const float*)d_in[16];
    const float* Wf1 = (const float*)d_in[17];
    const float* bf1 = (const float*)d_in[18];
    const float* Wf2 = (const float*)d_in[19];
    const float* bf2 = (const float*)d_in[20];

    float* h = (float*)d_out;
    float *hn, *q, *k, *v, *ao, *u;
    unsigned char* bins;
    cudaGetSymbolAddress((void**)&hn, g_hn);
    cudaGetSymbolAddress((void**)&q,  g_q);
    cudaGetSymbolAddress((void**)&k,  g_k);
    cudaGetSymbolAddress((void**)&v,  g_v);
    cudaGetSymbolAddress((void**)&ao, g_ao);
    cudaGetSymbolAddress((void**)&u,  g_u);
    cudaGetSymbolAddress((void**)&bins, g_bins);

    cudaMemcpyAsync(h, x, (size_t)ROWS*Hv*sizeof(float), cudaMemcpyDeviceToDevice);
    bins_kernel<<<(ROWS*Nv)/1024, 256>>>(dist, bins);

    dim3 gqkv(3, ROWS/128);          // fused QKV
    dim3 gone(1, ROWS/128);          // N=128 GEMMs
    dim3 gff1(2*FFv/128, ROWS/128);  // (8, 128)
    dim3 gattn(Nv/QT, NHv, Bv);      // (16, 8, 32)

    for (int l = 0; l < 3; l++) {
        ln_kernel<<<ROWS/8, 256>>>(h, g1 + l*Hv, b1 + l*Hv, hn);
        gemm_kernel<3><<<gqkv, 256>>>(hn,
            Wq + (size_t)l*Hv*Hv, bq + l*Hv, q,
            Wk + (size_t)l*Hv*Hv, bk + l*Hv, k,
            Wv + (size_t)l*Hv*Hv, bv + l*Hv, v,
            nullptr, Hv, Hv);
        attn_kernel<<<gattn, 256>>>(q, k, v, bins, mask,
                                    demb + (size_t)l*NBINS*NHv, ab + l*NHv, ao);
        gemm_kernel<1><<<gone, 256>>>(ao,
            Wo + (size_t)l*Hv*Hv, bo + l*Hv, h,
            nullptr, nullptr, nullptr, nullptr, nullptr, nullptr,
            h, Hv, Hv);
        ln_kernel<<<ROWS/8, 256>>>(h, g2 + l*Hv, b2 + l*Hv, hn);
        gemm_kernel<0><<<gff1, 256>>>(hn,
            Wf1 + (size_t)l*Hv*2*FFv, bf1 + (size_t)l*2*FFv, u,
            nullptr, nullptr, nullptr, nullptr, nullptr, nullptr,
            nullptr, Hv, 2*FFv);
        gemm_kernel<2><<<gone, 256>>>(u,
            Wf2 + (size_t)l*FFv*Hv, bf2 + l*Hv, h,
            nullptr, nullptr, nullptr, nullptr, nullptr, nullptr,
            h, FFv, Hv);
    }
}

// round 6
// speedup vs baseline: 2.1243x; 1.1959x over previous
#include <cuda_runtime.h>
#include <math.h>

#define Bv 32
#define Nv 512
#define Hv 128
#define NHv 8
#define HDv 16
#define FFv 512
#define NBINS 50
#define ROWS (Bv*Nv)   // 16384

typedef unsigned long long u64;

// ---------------- packed fp32x2 helpers (sm_103a FFMA2 path) ----------------
__device__ __forceinline__ u64 pack2(float x, float y){
    u64 r; asm("mov.b64 %0, {%1, %2};" : "=l"(r) : "f"(x), "f"(y)); return r;
}
__device__ __forceinline__ void unpack2(u64 v, float& x, float& y){
    asm("mov.b64 {%0, %1}, %2;" : "=f"(x), "=f"(y) : "l"(v));
}
__device__ __forceinline__ void fma2(u64& c, u64 a, u64 b){
    asm("fma.rn.f32x2 %0, %1, %2, %3;" : "=l"(c) : "l"(a), "l"(b), "l"(c));
}
__device__ __forceinline__ u64 mul2(u64 a, u64 b){
    u64 r; asm("mul.rn.f32x2 %0, %1, %2;" : "=l"(r) : "l"(a), "l"(b)); return r;
}

// ---------------- scratch (no allocations allowed) ----------------
__device__ float g_hn[ROWS*Hv];
__device__ float g_q [ROWS*Hv];
__device__ float g_k [ROWS*Hv];
__device__ float g_v [ROWS*Hv];
__device__ float g_ao[ROWS*Hv];
__device__ float g_u [ROWS*2*FFv];
__device__ unsigned char g_bins[(size_t)ROWS*Nv];   // 8.4 MB, fits L2

// ---------------- distance->bin precompute (once per launch) ----------------
__global__ __launch_bounds__(256) void bins_kernel(
    const float* __restrict__ dist, unsigned char* __restrict__ bins)
{
    int i = (blockIdx.x*256 + threadIdx.x) * 4;
    float4 d = *(const float4*)(dist + i);
    int b0 = (int)(d.x*10.f); b0 = b0<0?0:(b0>NBINS-1?NBINS-1:b0);
    int b1 = (int)(d.y*10.f); b1 = b1<0?0:(b1>NBINS-1?NBINS-1:b1);
    int b2 = (int)(d.z*10.f); b2 = b2<0?0:(b2>NBINS-1?NBINS-1:b2);
    int b3 = (int)(d.w*10.f); b3 = b3<0?0:(b3>NBINS-1?NBINS-1:b3);
    uchar4 o; o.x=(unsigned char)b0; o.y=(unsigned char)b1;
    o.z=(unsigned char)b2; o.w=(unsigned char)b3;
    *(uchar4*)(bins + i) = o;
}

// ---------------- LayerNorm: one warp per 128-wide row ----------------
__global__ __launch_bounds__(256) void ln_kernel(
    const float* __restrict__ h,
    const float* __restrict__ gamma,
    const float* __restrict__ beta,
    float* __restrict__ out)
{
    int row  = blockIdx.x * 8 + (threadIdx.x >> 5);
    int lane = threadIdx.x & 31;
    const float4* hp = (const float4*)(h + (size_t)row * Hv);
    float4 v = hp[lane];
    float s  = v.x + v.y + v.z + v.w;
    float ss = v.x*v.x + v.y*v.y + v.z*v.z + v.w*v.w;
    #pragma unroll
    for (int off = 16; off; off >>= 1) {
        s  += __shfl_xor_sync(0xffffffffu, s,  off);
        ss += __shfl_xor_sync(0xffffffffu, ss, off);
    }
    float mu  = s * (1.0f/Hv);
    float var = ss * (1.0f/Hv) - mu*mu;
    float inv = rsqrtf(var + 1e-5f);
    float4 g4 = ((const float4*)gamma)[lane];
    float4 b4 = ((const float4*)beta)[lane];
    float4 o;
    o.x = (v.x-mu)*inv*g4.x + b4.x;
    o.y = (v.y-mu)*inv*g4.y + b4.y;
    o.z = (v.z-mu)*inv*g4.z + b4.z;
    o.w = (v.w-mu)*inv*g4.w + b4.w;
    ((float4*)(out + (size_t)row*Hv))[lane] = o;
}

// ---------------- SGEMM: 128x128 tile, BK=16, 8x8 micro-tile, f32x2 FMA ----
// MODE: 0 = plain, 1 = +residual, 2 = GLU(A)+residual, 3 = fused QKV (3 W/b/C)
template<int MODE>
__global__ __launch_bounds__(256) void gemm_kernel(
    const float* __restrict__ A,
    const float* __restrict__ W0, const float* __restrict__ B0, float* __restrict__ C0,
    const float* __restrict__ W1, const float* __restrict__ B1c, float* __restrict__ C1,
    const float* __restrict__ W2, const float* __restrict__ B2c, float* __restrict__ C2,
    const float* __restrict__ R, int K, int Nc)
{
    __shared__ __align__(16) float As[2][16][132];
    __shared__ __align__(16) float Ws[2][16][128];
    const int tid = threadIdx.x;
    const float *W, *bias; float* C;
    int bn;
    if (MODE == 3) {
        int s = blockIdx.x;
        W    = (s==0)?W0:((s==1)?W1:W2);
        bias = (s==0)?B0:((s==1)?B1c:B2c);
        C    = (s==0)?C0:((s==1)?C1:C2);
        bn = 0;
    } else { W = W0; bias = B0; C = C0; bn = blockIdx.x * 128; }
    const int bm = blockIdx.y * 128;
    const int tx = tid & 15, ty = tid >> 4;
    const int ar = tid >> 1, ac = (tid & 1) * 8;   // A loader: row ar, 8 cols
    const int wr = tid >> 4, wc = (tid & 15) * 8;  // W loader: row wr, 8 cols
    const int ldA = (MODE==2) ? (2*FFv) : K;
    const float* Arow = A + (size_t)(bm + ar) * ldA;
    const float* Wp   = W + (size_t)wr * Nc + bn + wc;

    u64 acc[8][4];
    #pragma unroll
    for (int i=0;i<8;i++)
        #pragma unroll
        for (int j=0;j<4;j++) acc[i][j] = 0ull;

    float4 a0v, a1v, w0v, w1v;
    #define LOADT(k0) do { \
        if (MODE==2) { \
            float4 p0 = *(const float4*)(Arow + (k0) + ac); \
            float4 p1 = *(const float4*)(Arow + (k0) + ac + 4); \
            float4 s0 = *(const float4*)(Arow + FFv + (k0) + ac); \
            float4 s1 = *(const float4*)(Arow + FFv + (k0) + ac + 4); \
            a0v.x = p0.x/(1.f+__expf(-s0.x)); a0v.y = p0.y/(1.f+__expf(-s0.y)); \
            a0v.z = p0.z/(1.f+__expf(-s0.z)); a0v.w = p0.w/(1.f+__expf(-s0.w)); \
            a1v.x = p1.x/(1.f+__expf(-s1.x)); a1v.y = p1.y/(1.f+__expf(-s1.y)); \
            a1v.z = p1.z/(1.f+__expf(-s1.z)); a1v.w = p1.w/(1.f+__expf(-s1.w)); \
        } else { \
            a0v = *(const float4*)(Arow + (k0) + ac); \
            a1v = *(const float4*)(Arow + (k0) + ac + 4); \
        } \
        w0v = *(const float4*)(Wp + (size_t)(k0)*Nc); \
        w1v = *(const float4*)(Wp + (size_t)(k0)*Nc + 4); \
    } while(0)
    #define STORET(b) do { \
        As[b][ac+0][ar]=a0v.x; As[b][ac+1][ar]=a0v.y; \
        As[b][ac+2][ar]=a0v.z; As[b][ac+3][ar]=a0v.w; \
        As[b][ac+4][ar]=a1v.x; As[b][ac+5][ar]=a1v.y; \
        As[b][ac+6][ar]=a1v.z; As[b][ac+7][ar]=a1v.w; \
        *(float4*)&Ws[b][wr][wc]   = w0v; \
        *(float4*)&Ws[b][wr][wc+4] = w1v; \
    } while(0)

    LOADT(0); STORET(0); __syncthreads();
    const int nt = K/16;
    for (int t = 0; t < nt; t++) {
        int cur = t & 1;
        if (t+1 < nt) LOADT((t+1)*16);
        #pragma unroll
        for (int kk = 0; kk < 16; kk++) {
            float4 af0 = *(float4*)&As[cur][kk][ty*8];
            float4 af1 = *(float4*)&As[cur][kk][ty*8+4];
            const u64* bp = (const u64*)&Ws[cur][kk][tx*8];
            u64 b2[4]; b2[0]=bp[0]; b2[1]=bp[1]; b2[2]=bp[2]; b2[3]=bp[3];
            u64 as2[8];
            as2[0]=pack2(af0.x,af0.x); as2[1]=pack2(af0.y,af0.y);
            as2[2]=pack2(af0.z,af0.z); as2[3]=pack2(af0.w,af0.w);
            as2[4]=pack2(af1.x,af1.x); as2[5]=pack2(af1.y,af1.y);
            as2[6]=pack2(af1.z,af1.z); as2[7]=pack2(af1.w,af1.w);
            #pragma unroll
            for (int i=0;i<8;i++)
                #pragma unroll
                for (int j=0;j<4;j++) fma2(acc[i][j], as2[i], b2[j]);
        }
        if (t+1 < nt) STORET(cur^1);
        __syncthreads();
    }
    #undef LOADT
    #undef STORET

    const int cn = bn + tx*8;
    float4 bv0 = *(const float4*)(bias + cn);
    float4 bv1 = *(const float4*)(bias + cn + 4);
    #pragma unroll
    for (int i = 0; i < 8; i++) {
        int cm = bm + ty*8 + i;
        float c[8];
        #pragma unroll
        for (int j=0;j<4;j++) unpack2(acc[i][j], c[2*j], c[2*j+1]);
        c[0]+=bv0.x; c[1]+=bv0.y; c[2]+=bv0.z; c[3]+=bv0.w;
        c[4]+=bv1.x; c[5]+=bv1.y; c[6]+=bv1.z; c[7]+=bv1.w;
        if (MODE==1 || MODE==2) {
            float4 r0 = *(const float4*)(R + (size_t)cm*Nc + cn);
            float4 r1 = *(const float4*)(R + (size_t)cm*Nc + cn + 4);
            c[0]+=r0.x; c[1]+=r0.y; c[2]+=r0.z; c[3]+=r0.w;
            c[4]+=r1.x; c[5]+=r1.y; c[6]+=r1.z; c[7]+=r1.w;
        }
        float4 o0 = make_float4(c[0],c[1],c[2],c[3]);
        float4 o1 = make_float4(c[4],c[5],c[6],c[7]);
        *(float4*)(C + (size_t)cm*Nc + cn)     = o0;
        *(float4*)(C + (size_t)cm*Nc + cn + 4) = o1;
    }
}

// ---------------- fused attention v2 ----------------
// Block: (b, head, 64-query tile), 256 threads, KT=128 key tiles.
// Warp w: row group g=w>>1 (16 rows), key half h=w&1 (64 keys).
// Lane: 16 rows x 2 keys (k=64h+lane, +32) scores in registers.
// Single-pass softmax (register partials + tiny smem combine); P written once.
// PV: 2q x 2d blocking (4 outputs/thread), f32x2 packed over k.
#define QT2 64
#define KT2 128
#define QP 18
#define KP2 18
#define VP 134
#define SP2 132

#define SM_QS   0
#define SM_KS   (SM_QS + QT2*QP)        // 1152
#define SM_VT   (SM_KS + KT2*KP2)       // +2304
#define SM_P    (SM_VT + HDv*VP)        // +2144
#define SM_PM   (SM_P  + QT2*SP2)       // +8448
#define SM_PS   (SM_PM + 2*QT2)
#define SM_RM   (SM_PS + 2*QT2)
#define SM_RL   (SM_RM + QT2)
#define SM_RS   (SM_RL + QT2)
#define SM_SC0  (SM_RS + QT2)
#define SM_SC1  (SM_SC0 + QT2)
#define SM_DB   (SM_SC1 + QT2)
#define SM_MASK (SM_DB + 64)
#define ATTN_SMEM_FLOATS (SM_MASK + KT2)
#define ATTN_SMEM_BYTES  (ATTN_SMEM_FLOATS*4)

__global__ __launch_bounds__(256) void attn_kernel(
    const float* __restrict__ Q, const float* __restrict__ Kg,
    const float* __restrict__ V, const unsigned char* __restrict__ bins,
    const int* __restrict__ mask,
    const float* __restrict__ demb, const float* __restrict__ abias,
    float* __restrict__ AO)
{
    extern __shared__ __align__(16) float sm[];
    float* Qs = sm + SM_QS;
    float* Ks = sm + SM_KS;
    float* Vt = sm + SM_VT;
    float* P  = sm + SM_P;
    float* pm = sm + SM_PM;
    float* ps = sm + SM_PS;
    float* rowm = sm + SM_RM;
    float* rowl = sm + SM_RL;
    float* rsc  = sm + SM_RS;
    float* sc0  = sm + SM_SC0;
    float* sc1  = sm + SM_SC1;
    float* db   = sm + SM_DB;
    int*  maskt = (int*)(sm + SM_MASK);

    const int tid = threadIdx.x;
    const int qt = blockIdx.x, hh = blockIdx.y, bb = blockIdx.z;
    const int q0g = bb*Nv + qt*QT2;

    if (tid < NBINS) db[tid] = demb[tid*NHv + hh];
    if (tid < QT2) { rowm[tid] = -1e30f; rowl[tid] = 0.f; }
    {   // load Q tile [64 x 16]
        int r = tid >> 2, j = (tid & 3) << 2;
        float4 qv = *(const float4*)(Q + (size_t)(q0g + r)*Hv + hh*HDv + j);
        float* dst = &Qs[r*QP + j];
        *(float2*)dst     = make_float2(qv.x, qv.y);
        *(float2*)(dst+2) = make_float2(qv.z, qv.w);
    }
    const float ab = abias[hh];

    const int w = tid >> 5, lane = tid & 31;
    const int rowbase = (w >> 1) * 16;   // 0,16,32,48
    const int h = w & 1;
    const int k0l = 64*h + lane, k1l = k0l + 32;

    // PV mapping: 4 outputs/thread (rows qp, qp+32; dims 2dp, 2dp+1)
    const int qp = tid >> 3, dp = tid & 7;
    u64 a00 = 0ull, a01 = 0ull, a10 = 0ull, a11 = 0ull;

    float t0[16], t1[16];

    for (int kt = 0; kt < Nv/KT2; kt++) {
        const int kb = kt*KT2;
        __syncthreads();   // guard all tiles vs previous iteration consumers
        // --- load K (row-major) / V (transposed) tiles: 128 x 16 each ---
        #pragma unroll
        for (int ii = 0; ii < 2; ii++) {
            int id = tid + ii*256;
            int r = id >> 2, j = (id & 3) << 2;
            size_t goff = (size_t)(bb*Nv + kb + r)*Hv + hh*HDv + j;
            float4 kv = *(const float4*)(Kg + goff);
            float* kd = &Ks[r*KP2 + j];
            *(float2*)kd     = make_float2(kv.x, kv.y);
            *(float2*)(kd+2) = make_float2(kv.z, kv.w);
            float4 vv = *(const float4*)(V + goff);
            Vt[(j+0)*VP + r] = vv.x;
            Vt[(j+1)*VP + r] = vv.y;
            Vt[(j+2)*VP + r] = vv.z;
            Vt[(j+3)*VP + r] = vv.w;
        }
        if (tid < KT2) maskt[tid] = mask[bb*Nv + kb + tid];
        __syncthreads();

        // --- scores: 16 rows x 2 keys per lane ---
        u64 kr0[8], kr1[8];
        {
            const u64* p0 = (const u64*)&Ks[k0l*KP2];
            const u64* p1 = (const u64*)&Ks[k1l*KP2];
            #pragma unroll
            for (int d=0; d<8; d++) { kr0[d]=p0[d]; kr1[d]=p1[d]; }
        }
        const bool m0 = (maskt[k0l] != 0), m1 = (maskt[k1l] != 0);
        #pragma unroll
        for (int r = 0; r < 16; r++) {
            const u64* qr = (const u64*)&Qs[(rowbase + r)*QP];
            u64 s0p = 0ull, s1p = 0ull;
            #pragma unroll
            for (int d=0; d<8; d++) {
                u64 qd = qr[d];
                fma2(s0p, qd, kr0[d]);
                fma2(s1p, qd, kr1[d]);
            }
            float e, o;
            unpack2(s0p, e, o); float s0 = (e+o)*0.25f;
            unpack2(s1p, e, o); float s1 = (e+o)*0.25f;
            const unsigned char* brow = bins + (size_t)(q0g + rowbase + r)*Nv + kb;
            s0 = m0 ? -1e9f : (s0 + db[brow[k0l]] + ab);
            s1 = m1 ? -1e9f : (s1 + db[brow[k1l]] + ab);
            t0[r] = s0; t1[r] = s1;
        }
        // --- per-warp-half stats (max + sum of exp) ---
        #pragma unroll
        for (int r = 0; r < 16; r++) {
            float m = fmaxf(t0[r], t1[r]);
            #pragma unroll
            for (int off=16; off; off>>=1)
                m = fmaxf(m, __shfl_xor_sync(0xffffffffu, m, off));
            float e0 = __expf(t0[r] - m);
            float e1 = __expf(t1[r] - m);
            t0[r] = e0; t1[r] = e1;
            float s = e0 + e1;
            #pragma unroll
            for (int off=16; off; off>>=1)
                s += __shfl_xor_sync(0xffffffffu, s, off);
            if (lane == 0) {
                pm[h*QT2 + rowbase + r] = m;
                ps[h*QT2 + rowbase + r] = s;
            }
        }
        __syncthreads();
        // --- combine halves + running stats (one thread per row) ---
        if (tid < QT2) {
            int r = tid;
            float mA = pm[r], mB = pm[QT2 + r];
            float oldm = rowm[r];
            float nm = fmaxf(oldm, fmaxf(mA, mB));
            float so = __expf(oldm - nm);
            float sA = __expf(mA - nm);
            float sB = __expf(mB - nm);
            rowl[r] = rowl[r]*so + ps[r]*sA + ps[QT2 + r]*sB;
            rowm[r] = nm;
            rsc[r]  = so;
            sc0[r]  = sA;
            sc1[r]  = sB;
        }
        __syncthreads();
        // --- write P (scaled to common max) ---
        const float* schalf = h ? sc1 : sc0;
        #pragma unroll
        for (int r = 0; r < 16; r++) {
            float sc = schalf[rowbase + r];
            P[(rowbase + r)*SP2 + k0l] = t0[r]*sc;
            P[(rowbase + r)*SP2 + k1l] = t1[r]*sc;
        }
        __syncthreads();
        // --- PV: rescale accs, then accumulate this tile ---
        {
            u64 r0p = pack2(rsc[qp],    rsc[qp]);
            u64 r1p = pack2(rsc[qp+32], rsc[qp+32]);
            a00 = mul2(a00, r0p); a01 = mul2(a01, r0p);
            a10 = mul2(a10, r1p); a11 = mul2(a11, r1p);
            const u64* p0 = (const u64*)&P[qp*SP2];
            const u64* p1 = (const u64*)&P[(qp+32)*SP2];
            const u64* v0 = (const u64*)&Vt[(2*dp  )*VP];
            const u64* v1 = (const u64*)&Vt[(2*dp+1)*VP];
            #pragma unroll 8
            for (int k2 = 0; k2 < KT2/2; k2++) {
                u64 pa = p0[k2], pb = p1[k2];
                u64 va = v0[k2], vb = v1[k2];
                fma2(a00, pa, va); fma2(a01, pa, vb);
                fma2(a10, pb, va); fma2(a11, pb, vb);
            }
        }
    }
    // --- epilogue ---
    float inv0 = 1.0f / rowl[qp];
    float inv1 = 1.0f / rowl[qp+32];
    float e, o;
    float* out0 = AO + (size_t)(q0g + qp)*Hv + hh*HDv + 2*dp;
    float* out1 = AO + (size_t)(q0g + qp + 32)*Hv + hh*HDv + 2*dp;
    unpack2(a00, e, o); float o00 = (e+o)*inv0;
    unpack2(a01, e, o); float o01 = (e+o)*inv0;
    unpack2(a10, e, o); float o10 = (e+o)*inv1;
    unpack2(a11, e, o); float o11 = (e+o)*inv1;
    *(float2*)out0 = make_float2(o00, o01);
    *(float2*)out1 = make_float2(o10, o11);
}

// ---------------- launch ----------------
extern "C" void kernel_launch(void* const* d_in, const int* in_sizes, int n_in,
                              void* d_out, int out_size)
{
    const float* x    = (const float*)d_in[0];
    const float* dist = (const float*)d_in[1];
    const int*   mask = (const int*)d_in[2];
    const float* Wq  = (const float*)d_in[3];
    const float* bq  = (const float*)d_in[4];
    const float* Wk  = (const float*)d_in[5];
    const float* bk  = (const float*)d_in[6];
    const float* Wv  = (const float*)d_in[7];
    const float* bv  = (const float*)d_in[8];
    const float* Wo  = (const float*)d_in[9];
    const float* bo  = (const float*)d_in[10];
    const float* demb= (const float*)d_in[11];
    const float* ab  = (const float*)d_in[12];
    const float* g1  = (const float*)d_in[13];
    const float* b1  = (const float*)d_in[14];
    const float* g2  = (const float*)d_in[15];
    const float* b2  = (const float*)d_in[16];
    const float* Wf1 = (const float*)d_in[17];
    const float* bf1 = (const float*)d_in[18];
    const float* Wf2 = (const float*)d_in[19];
    const float* bf2 = (const float*)d_in[20];

    float* h = (float*)d_out;
    float *hn, *q, *k, *v, *ao, *u;
    unsigned char* bins;
    cudaGetSymbolAddress((void**)&hn, g_hn);
    cudaGetSymbolAddress((void**)&q,  g_q);
    cudaGetSymbolAddress((void**)&k,  g_k);
    cudaGetSymbolAddress((void**)&v,  g_v);
    cudaGetSymbolAddress((void**)&ao, g_ao);
    cudaGetSymbolAddress((void**)&u,  g_u);
    cudaGetSymbolAddress((void**)&bins, g_bins);

    cudaFuncSetAttribute(attn_kernel,
        cudaFuncAttributeMaxDynamicSharedMemorySize, ATTN_SMEM_BYTES);

    cudaMemcpyAsync(h, x, (size_t)ROWS*Hv*sizeof(float), cudaMemcpyDeviceToDevice);
    bins_kernel<<<(ROWS*Nv)/1024, 256>>>(dist, bins);

    dim3 gqkv(3, ROWS/128);          // fused QKV
    dim3 gone(1, ROWS/128);          // N=128 GEMMs
    dim3 gff1(2*FFv/128, ROWS/128);  // (8, 128)
    dim3 gattn(Nv/QT2, NHv, Bv);     // (8, 8, 32)

    for (int l = 0; l < 3; l++) {
        ln_kernel<<<ROWS/8, 256>>>(h, g1 + l*Hv, b1 + l*Hv, hn);
        gemm_kernel<3><<<gqkv, 256>>>(hn,
            Wq + (size_t)l*Hv*Hv, bq + l*Hv, q,
            Wk + (size_t)l*Hv*Hv, bk + l*Hv, k,
            Wv + (size_t)l*Hv*Hv, bv + l*Hv, v,
            nullptr, Hv, Hv);
        attn_kernel<<<gattn, 256, ATTN_SMEM_BYTES>>>(q, k, v, bins, mask,
                                    demb + (size_t)l*NBINS*NHv, ab + l*NHv, ao);
        gemm_kernel<1><<<gone, 256>>>(ao,
            Wo + (size_t)l*Hv*Hv, bo + l*Hv, h,
            nullptr, nullptr, nullptr, nullptr, nullptr, nullptr,
            h, Hv, Hv);
        ln_kernel<<<ROWS/8, 256>>>(h, g2 + l*Hv, b2 + l*Hv, hn);
        gemm_kernel<0><<<gff1, 256>>>(hn,
            Wf1 + (size_t)l*Hv*2*FFv, bf1 + (size_t)l*2*FFv, u,
            nullptr, nullptr, nullptr, nullptr, nullptr, nullptr,
            nullptr, Hv, 2*FFv);
        gemm_kernel<2><<<gone, 256>>>(u,
            Wf2 + (size_t)l*FFv*Hv, bf2 + l*Hv, h,
            nullptr, nullptr, nullptr, nullptr, nullptr, nullptr,
            h, FFv, Hv);
    }
}